// round 10
// baseline (speedup 1.0000x reference)
#include <cuda_runtime.h>
#include <cuda_fp16.h>
#include <cstdint>
#include <cstddef>

#define N_NODES 8192
#define F_DIM   512

// ============================================================================
// Scratch (device globals — no allocation anywhere)
// ============================================================================
__device__ __half g_adjT[(size_t)N_NODES * N_NODES];   // adjT[j][i] = adj[i][j]
__device__ __half g_XhT[(size_t)F_DIM * N_NODES];      // X hi, transposed [f][i]
__device__ __half g_XlT[(size_t)F_DIM * N_NODES];      // X lo, transposed [f][i]
__device__ __half g_WhT[(size_t)F_DIM * F_DIM];        // W hi, transposed [g][f]
__device__ __half g_WlT[(size_t)F_DIM * F_DIM];        // W lo, transposed [g][f]
__device__ __half g_Sh[(size_t)N_NODES * F_DIM];       // support hi [j][f]
__device__ __half g_Sl[(size_t)N_NODES * F_DIM];       // support lo [j][f]
__device__ float  g_deg[N_NODES];                      // in-degree per j

// ============================================================================
// Helpers (sm_80+ only — NOTHING arch-specific, target is sm_103 base)
// ============================================================================
__device__ __forceinline__ uint32_t smem_u32(const void* p) {
    uint32_t a;
    asm("{ .reg .u64 t; cvta.to.shared.u64 t, %1; cvt.u32.u64 %0, t; }"
        : "=r"(a) : "l"(p));
    return a;
}

__device__ __forceinline__ void cp_async16(uint32_t dst, const void* src) {
    asm volatile("cp.async.cg.shared.global [%0], [%1], 16;"
                 :: "r"(dst), "l"(src) : "memory");
}
#define CP_COMMIT() asm volatile("cp.async.commit_group;" ::: "memory")
#define CP_WAIT_1() asm volatile("cp.async.wait_group 1;" ::: "memory")
#define CP_WAIT_0() asm volatile("cp.async.wait_group 0;" ::: "memory")

// D += A * B  (m16n8k16, f16 inputs, f32 accumulate)
__device__ __forceinline__ void mma16816(float c[4], const uint32_t a[4],
                                         uint32_t b0, uint32_t b1) {
    asm volatile(
        "mma.sync.aligned.m16n8k16.row.col.f32.f16.f16.f32 "
        "{%0,%1,%2,%3}, {%4,%5,%6,%7}, {%8,%9}, {%0,%1,%2,%3};"
        : "+f"(c[0]), "+f"(c[1]), "+f"(c[2]), "+f"(c[3])
        : "r"(a[0]), "r"(a[1]), "r"(a[2]), "r"(a[3]), "r"(b0), "r"(b1));
}

// Tiles in SMEM: 128 rows x 32 k-halves, padded row stride = 40 halves (80 B).
// LDS.32 fragment reads are bank-conflict-free with this stride.
#define TSTRIDE   40
#define TILE_B    10240   // 128 * 40 * 2 bytes

// ============================================================================
// Kernel 0: zero degree accumulator
// ============================================================================
__global__ void zero_deg_kernel() {
    int i = blockIdx.x * blockDim.x + threadIdx.x;
    if (i < N_NODES) g_deg[i] = 0.0f;
}

// ============================================================================
// Kernel 1: transpose + hi/lo fp16 split.  in[R][C] fp32 -> out[C][R] half x2
// which==0 -> g_XhT/g_XlT, which==1 -> g_WhT/g_WlT
// ============================================================================
__global__ void transpose_split_kernel(const float* __restrict__ in,
                                       int R, int C, int which)
{
    __half* outH = which ? g_WhT : g_XhT;
    __half* outL = which ? g_WlT : g_XlT;
    __shared__ float tile[64][65];
    int r0 = blockIdx.y * 64;
    int c0 = blockIdx.x * 64;
    int tid = threadIdx.x;   // 256

    #pragma unroll
    for (int q = 0; q < 4; ++q) {
        int lin = q * 256 + tid;
        int r = lin >> 4;
        int c = (lin & 15) << 2;
        float4 v = *(const float4*)(in + (size_t)(r0 + r) * C + (c0 + c));
        tile[r][c] = v.x; tile[r][c+1] = v.y; tile[r][c+2] = v.z; tile[r][c+3] = v.w;
    }
    __syncthreads();

    int c = tid >> 2;
    #pragma unroll
    for (int sg = (tid & 3); sg < 8; sg += 4) {
        int rb = sg * 8;
        __align__(16) __half h[8];
        __align__(16) __half l[8];
        #pragma unroll
        for (int q = 0; q < 8; ++q) {
            float v = tile[rb + q][c];
            __half hh = __float2half_rn(v);
            h[q] = hh;
            l[q] = __float2half_rn(v - __half2float(hh));
        }
        *(uint4*)(outH + (size_t)(c0 + c) * R + r0 + rb) = *(const uint4*)h;
        *(uint4*)(outL + (size_t)(c0 + c) * R + r0 + rb) = *(const uint4*)l;
    }
}

// ============================================================================
// Kernel 2: adj int32 [N][N] -> adjT half [N][N] + in-degree (exact int sums)
// ============================================================================
__global__ void transpose_adj_kernel(const int* __restrict__ adj)
{
    __shared__ int tile[64][65];
    int i0 = blockIdx.y * 64;
    int j0 = blockIdx.x * 64;
    int tid = threadIdx.x;   // 256

    #pragma unroll
    for (int q = 0; q < 4; ++q) {
        int lin = q * 256 + tid;
        int r = lin >> 4;
        int c = (lin & 15) << 2;
        int4 v = *(const int4*)(adj + (size_t)(i0 + r) * N_NODES + (j0 + c));
        tile[r][c] = v.x; tile[r][c+1] = v.y; tile[r][c+2] = v.z; tile[r][c+3] = v.w;
    }
    __syncthreads();

    {   // exact integer partial column sums
        int c = tid & 63;
        int ch = tid >> 6;
        int s = 0;
        #pragma unroll
        for (int r = ch * 16; r < ch * 16 + 16; ++r) s += tile[r][c];
        atomicAdd(g_deg + j0 + c, (float)s);
    }

    int c = tid >> 2;
    #pragma unroll
    for (int sg = (tid & 3); sg < 8; sg += 4) {
        int rb = sg * 8;
        __align__(16) __half vals[8];
        #pragma unroll
        for (int q = 0; q < 8; ++q)
            vals[q] = __float2half_rn((float)tile[rb + q][c]);
        *(uint4*)(g_adjT + (size_t)(j0 + c) * N_NODES + i0 + rb) = *(const uint4*)vals;
    }
}

// ============================================================================
// Kernel 3: GEMM1 — support[j,f] = sum_i adjT[j][i] * (Xh+Xl)T[f][i]
// Grid (4 f-blocks, 64 j-blocks), 128x128 tile, 8 warps (4m x 2n), K chunks 32.
// Per chunk: tiles {A, Bh, Bl}; acc += A*Bh + A*Bl. Double-buffered cp.async.
// ============================================================================
#define G1_BUF_B   (3 * TILE_B)            // 30720
#define G1_SMEM    (2 * G1_BUF_B)          // 61440

__device__ __forceinline__ void g1_load(uint32_t sb, char* smem, int buf, int kc,
                                        int j0, int f0, int tid)
{
    (void)smem;
    const uint32_t base = sb + buf * G1_BUF_B;
    #pragma unroll
    for (int q = 0; q < 6; ++q) {               // 1536 segs / 256 threads
        int idx = q * 256 + tid;
        int t   = idx >> 9;                     // tile 0..2
        int rem = idx & 511;
        int r   = rem >> 2;
        int seg = rem & 3;
        const __half* src;
        if (t == 0)      src = g_adjT + (size_t)(j0 + r) * N_NODES + kc * 32 + seg * 8;
        else if (t == 1) src = g_XhT  + (size_t)(f0 + r) * N_NODES + kc * 32 + seg * 8;
        else             src = g_XlT  + (size_t)(f0 + r) * N_NODES + kc * 32 + seg * 8;
        cp_async16(base + t * TILE_B + r * 80 + seg * 16, src);
    }
    CP_COMMIT();
}

__global__ void __launch_bounds__(256, 2) gemm1_kernel()
{
    extern __shared__ char smem[];
    const uint32_t sb = smem_u32(smem);
    const int tid = threadIdx.x;
    const int wid = tid >> 5;
    const int lane = tid & 31;
    const int warp_m = wid & 3;
    const int warp_n = wid >> 2;
    const int gid  = lane >> 2;
    const int tig2 = (lane & 3) * 2;
    const int f0 = blockIdx.x * 128;
    const int j0 = blockIdx.y * 128;

    float acc[2][8][4];
    #pragma unroll
    for (int mi = 0; mi < 2; ++mi)
        #pragma unroll
        for (int ni = 0; ni < 8; ++ni)
            #pragma unroll
            for (int q = 0; q < 4; ++q) acc[mi][ni][q] = 0.0f;

    const int NC = N_NODES / 32;    // 256
    g1_load(sb, smem, 0, 0, j0, f0, tid);

    for (int c = 0; c < NC; ++c) {
        if (c + 1 < NC) { g1_load(sb, smem, (c + 1) & 1, c + 1, j0, f0, tid); CP_WAIT_1(); }
        else            { CP_WAIT_0(); }
        __syncthreads();

        const __half* As  = (const __half*)(smem + (c & 1) * G1_BUF_B);
        const __half* Bhs = As + TILE_B / 2;
        const __half* Bls = As + TILE_B;     // 2 * (TILE_B/2)

        #pragma unroll
        for (int kk = 0; kk < 32; kk += 16) {
            uint32_t a[2][4];
            #pragma unroll
            for (int mi = 0; mi < 2; ++mi) {
                int r0 = warp_m * 32 + mi * 16 + gid;
                a[mi][0] = *(const uint32_t*)&As[r0 * TSTRIDE + kk + tig2];
                a[mi][1] = *(const uint32_t*)&As[(r0 + 8) * TSTRIDE + kk + tig2];
                a[mi][2] = *(const uint32_t*)&As[r0 * TSTRIDE + kk + 8 + tig2];
                a[mi][3] = *(const uint32_t*)&As[(r0 + 8) * TSTRIDE + kk + 8 + tig2];
            }
            #pragma unroll
            for (int ni = 0; ni < 8; ++ni) {
                int nr = warp_n * 64 + ni * 8 + gid;
                uint32_t bh0 = *(const uint32_t*)&Bhs[nr * TSTRIDE + kk + tig2];
                uint32_t bh1 = *(const uint32_t*)&Bhs[nr * TSTRIDE + kk + 8 + tig2];
                uint32_t bl0 = *(const uint32_t*)&Bls[nr * TSTRIDE + kk + tig2];
                uint32_t bl1 = *(const uint32_t*)&Bls[nr * TSTRIDE + kk + 8 + tig2];
                mma16816(acc[0][ni], a[0], bh0, bh1);
                mma16816(acc[1][ni], a[1], bh0, bh1);
                mma16816(acc[0][ni], a[0], bl0, bl1);
                mma16816(acc[1][ni], a[1], bl0, bl1);
            }
        }
        __syncthreads();
    }

    // Epilogue: split fp32 support into Sh/Sl fp16
    #pragma unroll
    for (int mi = 0; mi < 2; ++mi) {
        #pragma unroll
        for (int ni = 0; ni < 8; ++ni) {
            int j = j0 + warp_m * 32 + mi * 16 + gid;
            int f = f0 + warp_n * 64 + ni * 8 + tig2;
            float v0 = acc[mi][ni][0], v1 = acc[mi][ni][1];
            float v2 = acc[mi][ni][2], v3 = acc[mi][ni][3];
            __half h0 = __float2half_rn(v0), h1 = __float2half_rn(v1);
            __half h2 = __float2half_rn(v2), h3 = __float2half_rn(v3);
            __half l0 = __float2half_rn(v0 - __half2float(h0));
            __half l1 = __float2half_rn(v1 - __half2float(h1));
            __half l2 = __float2half_rn(v2 - __half2float(h2));
            __half l3 = __float2half_rn(v3 - __half2float(h3));
            *(__half2*)&g_Sh[(size_t)j * F_DIM + f]       = __halves2half2(h0, h1);
            *(__half2*)&g_Sl[(size_t)j * F_DIM + f]       = __halves2half2(l0, l1);
            *(__half2*)&g_Sh[(size_t)(j + 8) * F_DIM + f] = __halves2half2(h2, h3);
            *(__half2*)&g_Sl[(size_t)(j + 8) * F_DIM + f] = __halves2half2(l2, l3);
        }
    }
}

// ============================================================================
// Kernel 4: GEMM2 + epilogue
// out[j,g] = relu( rsqrt(max(deg_j,1)) * sum_f (Sh+Sl)[j,f] (Wh+Wl)T[g,f] )
// Products hh + hl + lh (ll ~ 2^-44, dropped).
// ============================================================================
#define G2_BUF_B   (4 * TILE_B)            // 40960
#define G2_SMEM    (2 * G2_BUF_B)          // 81920

__device__ __forceinline__ void g2_load(uint32_t sb, int buf, int kc,
                                        int j0, int g0, int tid)
{
    const uint32_t base = sb + buf * G2_BUF_B;
    #pragma unroll
    for (int q = 0; q < 8; ++q) {               // 2048 segs / 256 threads
        int idx = q * 256 + tid;
        int t   = idx >> 9;                     // tile 0..3: Ah, Al, Bh, Bl
        int rem = idx & 511;
        int r   = rem >> 2;
        int seg = rem & 3;
        const __half* src;
        if (t == 0)      src = g_Sh  + (size_t)(j0 + r) * F_DIM + kc * 32 + seg * 8;
        else if (t == 1) src = g_Sl  + (size_t)(j0 + r) * F_DIM + kc * 32 + seg * 8;
        else if (t == 2) src = g_WhT + (size_t)(g0 + r) * F_DIM + kc * 32 + seg * 8;
        else             src = g_WlT + (size_t)(g0 + r) * F_DIM + kc * 32 + seg * 8;
        cp_async16(base + t * TILE_B + r * 80 + seg * 16, src);
    }
    CP_COMMIT();
}

__global__ void __launch_bounds__(256, 2) gemm2_kernel(float* __restrict__ out)
{
    extern __shared__ char smem[];
    const uint32_t sb = smem_u32(smem);
    const int tid = threadIdx.x;
    const int wid = tid >> 5;
    const int lane = tid & 31;
    const int warp_m = wid & 3;
    const int warp_n = wid >> 2;
    const int gid  = lane >> 2;
    const int tig2 = (lane & 3) * 2;
    const int g0 = blockIdx.x * 128;
    const int j0 = blockIdx.y * 128;

    float acc[2][8][4];
    #pragma unroll
    for (int mi = 0; mi < 2; ++mi)
        #pragma unroll
        for (int ni = 0; ni < 8; ++ni)
            #pragma unroll
            for (int q = 0; q < 4; ++q) acc[mi][ni][q] = 0.0f;

    const int NC = F_DIM / 32;   // 16
    g2_load(sb, 0, 0, j0, g0, tid);

    for (int c = 0; c < NC; ++c) {
        if (c + 1 < NC) { g2_load(sb, (c + 1) & 1, c + 1, j0, g0, tid); CP_WAIT_1(); }
        else            { CP_WAIT_0(); }
        __syncthreads();

        const __half* Ahs = (const __half*)(smem + (c & 1) * G2_BUF_B);
        const __half* Als = Ahs + TILE_B / 2;
        const __half* Bhs = Ahs + TILE_B;
        const __half* Bls = Ahs + 3 * TILE_B / 2;

        #pragma unroll
        for (int kk = 0; kk < 32; kk += 16) {
            uint32_t ah[2][4], al[2][4];
            #pragma unroll
            for (int mi = 0; mi < 2; ++mi) {
                int r0 = warp_m * 32 + mi * 16 + gid;
                ah[mi][0] = *(const uint32_t*)&Ahs[r0 * TSTRIDE + kk + tig2];
                ah[mi][1] = *(const uint32_t*)&Ahs[(r0 + 8) * TSTRIDE + kk + tig2];
                ah[mi][2] = *(const uint32_t*)&Ahs[r0 * TSTRIDE + kk + 8 + tig2];
                ah[mi][3] = *(const uint32_t*)&Ahs[(r0 + 8) * TSTRIDE + kk + 8 + tig2];
                al[mi][0] = *(const uint32_t*)&Als[r0 * TSTRIDE + kk + tig2];
                al[mi][1] = *(const uint32_t*)&Als[(r0 + 8) * TSTRIDE + kk + tig2];
                al[mi][2] = *(const uint32_t*)&Als[r0 * TSTRIDE + kk + 8 + tig2];
                al[mi][3] = *(const uint32_t*)&Als[(r0 + 8) * TSTRIDE + kk + 8 + tig2];
            }
            #pragma unroll
            for (int ni = 0; ni < 8; ++ni) {
                int nr = warp_n * 64 + ni * 8 + gid;
                uint32_t bh0 = *(const uint32_t*)&Bhs[nr * TSTRIDE + kk + tig2];
                uint32_t bh1 = *(const uint32_t*)&Bhs[nr * TSTRIDE + kk + 8 + tig2];
                uint32_t bl0 = *(const uint32_t*)&Bls[nr * TSTRIDE + kk + tig2];
                uint32_t bl1 = *(const uint32_t*)&Bls[nr * TSTRIDE + kk + 8 + tig2];
                #pragma unroll
                for (int mi = 0; mi < 2; ++mi) {
                    mma16816(acc[mi][ni], ah[mi], bh0, bh1);   // hh
                    mma16816(acc[mi][ni], ah[mi], bl0, bl1);   // hl
                    mma16816(acc[mi][ni], al[mi], bh0, bh1);   // lh
                }
            }
        }
        __syncthreads();
    }

    // Epilogue: norm + relu, fp32 output
    #pragma unroll
    for (int mi = 0; mi < 2; ++mi) {
        int j = j0 + warp_m * 32 + mi * 16 + gid;
        float nrm0 = rsqrtf(fmaxf(g_deg[j], 1.0f));
        float nrm1 = rsqrtf(fmaxf(g_deg[j + 8], 1.0f));
        #pragma unroll
        for (int ni = 0; ni < 8; ++ni) {
            int g = g0 + warp_n * 64 + ni * 8 + tig2;
            float2 v0, v1;
            v0.x = fmaxf(acc[mi][ni][0] * nrm0, 0.0f);
            v0.y = fmaxf(acc[mi][ni][1] * nrm0, 0.0f);
            v1.x = fmaxf(acc[mi][ni][2] * nrm1, 0.0f);
            v1.y = fmaxf(acc[mi][ni][3] * nrm1, 0.0f);
            *(float2*)(out + (size_t)j * F_DIM + g)       = v0;
            *(float2*)(out + (size_t)(j + 8) * F_DIM + g) = v1;
        }
    }
}

// ============================================================================
// Launch
// ============================================================================
extern "C" void kernel_launch(void* const* d_in, const int* in_sizes, int n_in,
                              void* d_out, int out_size)
{
    (void)in_sizes; (void)n_in; (void)out_size;
    const float* X      = (const float*)d_in[0];   // [8192, 512]
    const int*   adj    = (const int*)d_in[1];     // [8192, 8192]
    const float* weight = (const float*)d_in[2];   // [512, 512]
    float* out = (float*)d_out;                    // [8192, 512]

    static bool attr_done = false;
    if (!attr_done) {
        cudaFuncSetAttribute(gemm1_kernel,
            cudaFuncAttributeMaxDynamicSharedMemorySize, G1_SMEM);
        cudaFuncSetAttribute(gemm2_kernel,
            cudaFuncAttributeMaxDynamicSharedMemorySize, G2_SMEM);
        attr_done = true;
    }

    zero_deg_kernel<<<N_NODES / 256, 256>>>();

    {   // X: [8192, 512] -> XhT/XlT [512, 8192]
        dim3 grid(F_DIM / 64, N_NODES / 64);
        transpose_split_kernel<<<grid, 256>>>(X, N_NODES, F_DIM, 0);
    }
    {   // W: [512, 512] -> WhT/WlT [512, 512]
        dim3 grid(F_DIM / 64, F_DIM / 64);
        transpose_split_kernel<<<grid, 256>>>(weight, F_DIM, F_DIM, 1);
    }
    {   // adj -> adjT half + degrees
        dim3 grid(N_NODES / 64, N_NODES / 64);
        transpose_adj_kernel<<<grid, 256>>>(adj);
    }

    {   // GEMM1: support = adjT @ (Xh + Xl)
        dim3 grid(F_DIM / 128, N_NODES / 128);   // (4, 64)
        gemm1_kernel<<<grid, 256, G1_SMEM>>>();
    }
    {   // GEMM2 + norm + relu
        dim3 grid(F_DIM / 128, N_NODES / 128);   // (4, 64)
        gemm2_kernel<<<grid, 256, G2_SMEM>>>(out);
    }
}

// round 12
// speedup vs baseline: 1.6788x; 1.6788x over previous
#include <cuda_runtime.h>
#include <cuda_fp16.h>
#include <cstdint>
#include <cstddef>

#define N_NODES 8192
#define F_DIM   512

// ============================================================================
// Scratch (device globals — no allocation anywhere)
// ============================================================================
__device__ __half g_adjT[(size_t)N_NODES * N_NODES];   // adjT[j][i] = adj[i][j]
__device__ __half g_XhT[(size_t)F_DIM * N_NODES];      // X hi, transposed [f][i]
__device__ __half g_XlT[(size_t)F_DIM * N_NODES];      // X lo (unused by GEMM1 now)
__device__ __half g_WhT[(size_t)F_DIM * F_DIM];        // W hi, transposed [g][f]
__device__ __half g_WlT[(size_t)F_DIM * F_DIM];        // W lo, transposed [g][f]
__device__ __half g_Sh[(size_t)N_NODES * F_DIM];       // support hi [j][f]
__device__ __half g_Sl[(size_t)N_NODES * F_DIM];       // support lo [j][f]
__device__ float  g_deg[N_NODES];                      // in-degree per j

// ============================================================================
// Helpers (sm_80+ only — target is sm_103 BASE, no tcgen05 / no "a" features)
// ============================================================================
__device__ __forceinline__ uint32_t smem_u32(const void* p) {
    uint32_t a;
    asm("{ .reg .u64 t; cvta.to.shared.u64 t, %1; cvt.u32.u64 %0, t; }"
        : "=r"(a) : "l"(p));
    return a;
}

__device__ __forceinline__ void cp_async16(uint32_t dst, const void* src) {
    asm volatile("cp.async.cg.shared.global [%0], [%1], 16;"
                 :: "r"(dst), "l"(src) : "memory");
}
#define CP_COMMIT() asm volatile("cp.async.commit_group;" ::: "memory")
#define CP_WAIT_1() asm volatile("cp.async.wait_group 1;" ::: "memory")
#define CP_WAIT_0() asm volatile("cp.async.wait_group 0;" ::: "memory")

// D += A * B  (m16n8k16, f16 inputs, f32 accumulate)
__device__ __forceinline__ void mma16816(float c[4], const uint32_t a[4],
                                         uint32_t b0, uint32_t b1) {
    asm volatile(
        "mma.sync.aligned.m16n8k16.row.col.f32.f16.f16.f32 "
        "{%0,%1,%2,%3}, {%4,%5,%6,%7}, {%8,%9}, {%0,%1,%2,%3};"
        : "+f"(c[0]), "+f"(c[1]), "+f"(c[2]), "+f"(c[3])
        : "r"(a[0]), "r"(a[1]), "r"(a[2]), "r"(a[3]), "r"(b0), "r"(b1));
}

// GEMM2 tiles: 128 rows x 32 k-halves, padded row stride = 40 halves (80 B).
#define TSTRIDE   40
#define TILE_B    10240   // 128 * 40 * 2

// GEMM1 tiles: 128 rows x 64 k-halves, padded row stride = 72 halves (144 B).
// Frag-load banks: (r*36 + tig) mod 32 -> all 32 distinct. Conflict-free.
#define TSTRIDE1  72
#define TILE1_B   18432   // 128 * 72 * 2

// ============================================================================
// Kernel 0: zero degree accumulator
// ============================================================================
__global__ void zero_deg_kernel() {
    int i = blockIdx.x * blockDim.x + threadIdx.x;
    if (i < N_NODES) g_deg[i] = 0.0f;
}

// ============================================================================
// Kernel 1: transpose + hi/lo fp16 split.  in[R][C] fp32 -> out[C][R] half x2
// which==0 -> g_XhT/g_XlT, which==1 -> g_WhT/g_WlT
// ============================================================================
__global__ void transpose_split_kernel(const float* __restrict__ in,
                                       int R, int C, int which)
{
    __half* outH = which ? g_WhT : g_XhT;
    __half* outL = which ? g_WlT : g_XlT;
    __shared__ float tile[64][65];
    int r0 = blockIdx.y * 64;
    int c0 = blockIdx.x * 64;
    int tid = threadIdx.x;   // 256

    #pragma unroll
    for (int q = 0; q < 4; ++q) {
        int lin = q * 256 + tid;
        int r = lin >> 4;
        int c = (lin & 15) << 2;
        float4 v = *(const float4*)(in + (size_t)(r0 + r) * C + (c0 + c));
        tile[r][c] = v.x; tile[r][c+1] = v.y; tile[r][c+2] = v.z; tile[r][c+3] = v.w;
    }
    __syncthreads();

    int c = tid >> 2;
    #pragma unroll
    for (int sg = (tid & 3); sg < 8; sg += 4) {
        int rb = sg * 8;
        __align__(16) __half h[8];
        __align__(16) __half l[8];
        #pragma unroll
        for (int q = 0; q < 8; ++q) {
            float v = tile[rb + q][c];
            __half hh = __float2half_rn(v);
            h[q] = hh;
            l[q] = __float2half_rn(v - __half2float(hh));
        }
        *(uint4*)(outH + (size_t)(c0 + c) * R + r0 + rb) = *(const uint4*)h;
        *(uint4*)(outL + (size_t)(c0 + c) * R + r0 + rb) = *(const uint4*)l;
    }
}

// ============================================================================
// Kernel 2: adj int32 [N][N] -> adjT half [N][N] + in-degree (exact int sums)
// ============================================================================
__global__ void transpose_adj_kernel(const int* __restrict__ adj)
{
    __shared__ int tile[64][65];
    int i0 = blockIdx.y * 64;
    int j0 = blockIdx.x * 64;
    int tid = threadIdx.x;   // 256

    #pragma unroll
    for (int q = 0; q < 4; ++q) {
        int lin = q * 256 + tid;
        int r = lin >> 4;
        int c = (lin & 15) << 2;
        int4 v = *(const int4*)(adj + (size_t)(i0 + r) * N_NODES + (j0 + c));
        tile[r][c] = v.x; tile[r][c+1] = v.y; tile[r][c+2] = v.z; tile[r][c+3] = v.w;
    }
    __syncthreads();

    {   // exact integer partial column sums
        int c = tid & 63;
        int ch = tid >> 6;
        int s = 0;
        #pragma unroll
        for (int r = ch * 16; r < ch * 16 + 16; ++r) s += tile[r][c];
        atomicAdd(g_deg + j0 + c, (float)s);
    }

    int c = tid >> 2;
    #pragma unroll
    for (int sg = (tid & 3); sg < 8; sg += 4) {
        int rb = sg * 8;
        __align__(16) __half vals[8];
        #pragma unroll
        for (int q = 0; q < 8; ++q)
            vals[q] = __float2half_rn((float)tile[rb + q][c]);
        *(uint4*)(g_adjT + (size_t)(j0 + c) * N_NODES + i0 + rb) = *(const uint4*)vals;
    }
}

// ============================================================================
// Kernel 3: GEMM1 — support[j,f] = sum_i adjT[j][i] * XhT[f][i]
// (Xl product dropped: adj is exact in fp16; error ~1.4e-4 << 1e-3 gate.)
// Grid (4 f-blocks, 64 j-blocks), 128x128 tile, 8 warps (4m x 2n), K chunk 64.
// Double-buffered cp.async; 2 CTAs/SM (smem 72KB/CTA).
// ============================================================================
#define G1_BUF_B   (2 * TILE1_B)           // 36864: {A, Bh}
#define G1_SMEM    (2 * G1_BUF_B)          // 73728

__device__ __forceinline__ void g1_load(uint32_t sb, int buf, int kc,
                                        int j0, int f0, int tid)
{
    const uint32_t base = sb + buf * G1_BUF_B;
    #pragma unroll
    for (int q = 0; q < 8; ++q) {               // 2048 segs / 256 threads
        int idx = q * 256 + tid;
        int t   = idx >> 10;                    // 0 = A(adjT), 1 = B(XhT)
        int rem = idx & 1023;
        int r   = rem >> 3;
        int seg = rem & 7;
        const __half* src = t
            ? g_XhT  + (size_t)(f0 + r) * N_NODES + kc * 64 + seg * 8
            : g_adjT + (size_t)(j0 + r) * N_NODES + kc * 64 + seg * 8;
        cp_async16(base + t * TILE1_B + r * 144 + seg * 16, src);
    }
    CP_COMMIT();
}

__global__ void __launch_bounds__(256, 2) gemm1_kernel()
{
    extern __shared__ char smem[];
    const uint32_t sb = smem_u32(smem);
    const int tid = threadIdx.x;
    const int wid = tid >> 5;
    const int lane = tid & 31;
    const int warp_m = wid & 3;
    const int warp_n = wid >> 2;
    const int gid  = lane >> 2;
    const int tig2 = (lane & 3) * 2;
    const int f0 = blockIdx.x * 128;
    const int j0 = blockIdx.y * 128;

    float acc[2][8][4];
    #pragma unroll
    for (int mi = 0; mi < 2; ++mi)
        #pragma unroll
        for (int ni = 0; ni < 8; ++ni)
            #pragma unroll
            for (int q = 0; q < 4; ++q) acc[mi][ni][q] = 0.0f;

    const int NC = N_NODES / 64;    // 128
    g1_load(sb, 0, 0, j0, f0, tid);

    for (int c = 0; c < NC; ++c) {
        if (c + 1 < NC) { g1_load(sb, (c + 1) & 1, c + 1, j0, f0, tid); CP_WAIT_1(); }
        else            { CP_WAIT_0(); }
        __syncthreads();

        const __half* As = (const __half*)(smem + (c & 1) * G1_BUF_B);
        const __half* Bs = As + TILE1_B / 2;    // halves

        #pragma unroll
        for (int kk = 0; kk < 64; kk += 16) {
            uint32_t a[2][4];
            #pragma unroll
            for (int mi = 0; mi < 2; ++mi) {
                int r0 = warp_m * 32 + mi * 16 + gid;
                a[mi][0] = *(const uint32_t*)&As[r0 * TSTRIDE1 + kk + tig2];
                a[mi][1] = *(const uint32_t*)&As[(r0 + 8) * TSTRIDE1 + kk + tig2];
                a[mi][2] = *(const uint32_t*)&As[r0 * TSTRIDE1 + kk + 8 + tig2];
                a[mi][3] = *(const uint32_t*)&As[(r0 + 8) * TSTRIDE1 + kk + 8 + tig2];
            }
            #pragma unroll
            for (int ni = 0; ni < 8; ++ni) {
                int nr = warp_n * 64 + ni * 8 + gid;
                uint32_t b0 = *(const uint32_t*)&Bs[nr * TSTRIDE1 + kk + tig2];
                uint32_t b1 = *(const uint32_t*)&Bs[nr * TSTRIDE1 + kk + 8 + tig2];
                mma16816(acc[0][ni], a[0], b0, b1);
                mma16816(acc[1][ni], a[1], b0, b1);
            }
        }
        __syncthreads();
    }

    // Epilogue: split fp32 support into Sh/Sl fp16
    #pragma unroll
    for (int mi = 0; mi < 2; ++mi) {
        #pragma unroll
        for (int ni = 0; ni < 8; ++ni) {
            int j = j0 + warp_m * 32 + mi * 16 + gid;
            int f = f0 + warp_n * 64 + ni * 8 + tig2;
            float v0 = acc[mi][ni][0], v1 = acc[mi][ni][1];
            float v2 = acc[mi][ni][2], v3 = acc[mi][ni][3];
            __half h0 = __float2half_rn(v0), h1 = __float2half_rn(v1);
            __half h2 = __float2half_rn(v2), h3 = __float2half_rn(v3);
            __half l0 = __float2half_rn(v0 - __half2float(h0));
            __half l1 = __float2half_rn(v1 - __half2float(h1));
            __half l2 = __float2half_rn(v2 - __half2float(h2));
            __half l3 = __float2half_rn(v3 - __half2float(h3));
            *(__half2*)&g_Sh[(size_t)j * F_DIM + f]       = __halves2half2(h0, h1);
            *(__half2*)&g_Sl[(size_t)j * F_DIM + f]       = __halves2half2(l0, l1);
            *(__half2*)&g_Sh[(size_t)(j + 8) * F_DIM + f] = __halves2half2(h2, h3);
            *(__half2*)&g_Sl[(size_t)(j + 8) * F_DIM + f] = __halves2half2(l2, l3);
        }
    }
}

// ============================================================================
// Kernel 4: GEMM2 + epilogue
// out[j,g] = relu( rsqrt(max(deg_j,1)) * sum_f (Sh+Sl)[j,f] (Wh+Wl)T[g,f] )
// Products hh + hl + lh (ll dropped).
// ============================================================================
#define G2_BUF_B   (4 * TILE_B)            // 40960
#define G2_SMEM    (2 * G2_BUF_B)          // 81920

__device__ __forceinline__ void g2_load(uint32_t sb, int buf, int kc,
                                        int j0, int g0, int tid)
{
    const uint32_t base = sb + buf * G2_BUF_B;
    #pragma unroll
    for (int q = 0; q < 8; ++q) {               // 2048 segs / 256 threads
        int idx = q * 256 + tid;
        int t   = idx >> 9;                     // tile 0..3: Ah, Al, Bh, Bl
        int rem = idx & 511;
        int r   = rem >> 2;
        int seg = rem & 3;
        const __half* src;
        if (t == 0)      src = g_Sh  + (size_t)(j0 + r) * F_DIM + kc * 32 + seg * 8;
        else if (t == 1) src = g_Sl  + (size_t)(j0 + r) * F_DIM + kc * 32 + seg * 8;
        else if (t == 2) src = g_WhT + (size_t)(g0 + r) * F_DIM + kc * 32 + seg * 8;
        else             src = g_WlT + (size_t)(g0 + r) * F_DIM + kc * 32 + seg * 8;
        cp_async16(base + t * TILE_B + r * 80 + seg * 16, src);
    }
    CP_COMMIT();
}

__global__ void __launch_bounds__(256, 2) gemm2_kernel(float* __restrict__ out)
{
    extern __shared__ char smem[];
    const uint32_t sb = smem_u32(smem);
    const int tid = threadIdx.x;
    const int wid = tid >> 5;
    const int lane = tid & 31;
    const int warp_m = wid & 3;
    const int warp_n = wid >> 2;
    const int gid  = lane >> 2;
    const int tig2 = (lane & 3) * 2;
    const int g0 = blockIdx.x * 128;
    const int j0 = blockIdx.y * 128;

    float acc[2][8][4];
    #pragma unroll
    for (int mi = 0; mi < 2; ++mi)
        #pragma unroll
        for (int ni = 0; ni < 8; ++ni)
            #pragma unroll
            for (int q = 0; q < 4; ++q) acc[mi][ni][q] = 0.0f;

    const int NC = F_DIM / 32;   // 16
    g2_load(sb, 0, 0, j0, g0, tid);

    for (int c = 0; c < NC; ++c) {
        if (c + 1 < NC) { g2_load(sb, (c + 1) & 1, c + 1, j0, g0, tid); CP_WAIT_1(); }
        else            { CP_WAIT_0(); }
        __syncthreads();

        const __half* Ahs = (const __half*)(smem + (c & 1) * G2_BUF_B);
        const __half* Als = Ahs + TILE_B / 2;
        const __half* Bhs = Ahs + TILE_B;
        const __half* Bls = Ahs + 3 * TILE_B / 2;

        #pragma unroll
        for (int kk = 0; kk < 32; kk += 16) {
            uint32_t ah[2][4], al[2][4];
            #pragma unroll
            for (int mi = 0; mi < 2; ++mi) {
                int r0 = warp_m * 32 + mi * 16 + gid;
                ah[mi][0] = *(const uint32_t*)&Ahs[r0 * TSTRIDE + kk + tig2];
                ah[mi][1] = *(const uint32_t*)&Ahs[(r0 + 8) * TSTRIDE + kk + tig2];
                ah[mi][2] = *(const uint32_t*)&Ahs[r0 * TSTRIDE + kk + 8 + tig2];
                ah[mi][3] = *(const uint32_t*)&Ahs[(r0 + 8) * TSTRIDE + kk + 8 + tig2];
                al[mi][0] = *(const uint32_t*)&Als[r0 * TSTRIDE + kk + tig2];
                al[mi][1] = *(const uint32_t*)&Als[(r0 + 8) * TSTRIDE + kk + tig2];
                al[mi][2] = *(const uint32_t*)&Als[r0 * TSTRIDE + kk + 8 + tig2];
                al[mi][3] = *(const uint32_t*)&Als[(r0 + 8) * TSTRIDE + kk + 8 + tig2];
            }
            #pragma unroll
            for (int ni = 0; ni < 8; ++ni) {
                int nr = warp_n * 64 + ni * 8 + gid;
                uint32_t bh0 = *(const uint32_t*)&Bhs[nr * TSTRIDE + kk + tig2];
                uint32_t bh1 = *(const uint32_t*)&Bhs[nr * TSTRIDE + kk + 8 + tig2];
                uint32_t bl0 = *(const uint32_t*)&Bls[nr * TSTRIDE + kk + tig2];
                uint32_t bl1 = *(const uint32_t*)&Bls[nr * TSTRIDE + kk + 8 + tig2];
                #pragma unroll
                for (int mi = 0; mi < 2; ++mi) {
                    mma16816(acc[mi][ni], ah[mi], bh0, bh1);   // hh
                    mma16816(acc[mi][ni], ah[mi], bl0, bl1);   // hl
                    mma16816(acc[mi][ni], al[mi], bh0, bh1);   // lh
                }
            }
        }
        __syncthreads();
    }

    // Epilogue: norm + relu, fp32 output
    #pragma unroll
    for (int mi = 0; mi < 2; ++mi) {
        int j = j0 + warp_m * 32 + mi * 16 + gid;
        float nrm0 = rsqrtf(fmaxf(g_deg[j], 1.0f));
        float nrm1 = rsqrtf(fmaxf(g_deg[j + 8], 1.0f));
        #pragma unroll
        for (int ni = 0; ni < 8; ++ni) {
            int g = g0 + warp_n * 64 + ni * 8 + tig2;
            float2 v0, v1;
            v0.x = fmaxf(acc[mi][ni][0] * nrm0, 0.0f);
            v0.y = fmaxf(acc[mi][ni][1] * nrm0, 0.0f);
            v1.x = fmaxf(acc[mi][ni][2] * nrm1, 0.0f);
            v1.y = fmaxf(acc[mi][ni][3] * nrm1, 0.0f);
            *(float2*)(out + (size_t)j * F_DIM + g)       = v0;
            *(float2*)(out + (size_t)(j + 8) * F_DIM + g) = v1;
        }
    }
}

// ============================================================================
// Launch
// ============================================================================
extern "C" void kernel_launch(void* const* d_in, const int* in_sizes, int n_in,
                              void* d_out, int out_size)
{
    (void)in_sizes; (void)n_in; (void)out_size;
    const float* X      = (const float*)d_in[0];   // [8192, 512]
    const int*   adj    = (const int*)d_in[1];     // [8192, 8192]
    const float* weight = (const float*)d_in[2];   // [512, 512]
    float* out = (float*)d_out;                    // [8192, 512]

    static bool attr_done = false;
    if (!attr_done) {
        cudaFuncSetAttribute(gemm1_kernel,
            cudaFuncAttributeMaxDynamicSharedMemorySize, G1_SMEM);
        cudaFuncSetAttribute(gemm2_kernel,
            cudaFuncAttributeMaxDynamicSharedMemorySize, G2_SMEM);
        attr_done = true;
    }

    zero_deg_kernel<<<N_NODES / 256, 256>>>();

    {   // X: [8192, 512] -> XhT/XlT [512, 8192]
        dim3 grid(F_DIM / 64, N_NODES / 64);
        transpose_split_kernel<<<grid, 256>>>(X, N_NODES, F_DIM, 0);
    }
    {   // W: [512, 512] -> WhT/WlT [512, 512]
        dim3 grid(F_DIM / 64, F_DIM / 64);
        transpose_split_kernel<<<grid, 256>>>(weight, F_DIM, F_DIM, 1);
    }
    {   // adj -> adjT half + degrees
        dim3 grid(N_NODES / 64, N_NODES / 64);
        transpose_adj_kernel<<<grid, 256>>>(adj);
    }

    {   // GEMM1: support = adjT @ Xh
        dim3 grid(F_DIM / 128, N_NODES / 128);   // (4, 64)
        gemm1_kernel<<<grid, 256, G1_SMEM>>>();
    }
    {   // GEMM2 + norm + relu
        dim3 grid(F_DIM / 128, N_NODES / 128);   // (4, 64)
        gemm2_kernel<<<grid, 256, G2_SMEM>>>(out);
    }
}

// round 13
// speedup vs baseline: 1.7669x; 1.0525x over previous
#include <cuda_runtime.h>
#include <cuda_fp16.h>
#include <cstdint>
#include <cstddef>

#define N_NODES 8192
#define F_DIM   512
#define NW      (N_NODES / 32)   // 256 words per packed row

// ============================================================================
// Scratch (device globals — no allocation anywhere)
// ============================================================================
__device__ uint32_t g_adjP[(size_t)N_NODES * NW];      // bit b of [j][w] = adj[32w+b][j]
__device__ __half g_XhT[(size_t)F_DIM * N_NODES];      // X hi, transposed [f][i]
__device__ __half g_XlT[(size_t)F_DIM * N_NODES];      // X lo (kept for split kernel)
__device__ __half g_WhT[(size_t)F_DIM * F_DIM];        // W hi, transposed [g][f]
__device__ __half g_WlT[(size_t)F_DIM * F_DIM];        // W lo, transposed [g][f]
__device__ __half g_Sh[(size_t)N_NODES * F_DIM];       // support hi [j][f]
__device__ __half g_Sl[(size_t)N_NODES * F_DIM];       // support lo [j][f]
__device__ float  g_deg[N_NODES];                      // in-degree per j

// ============================================================================
// Helpers (sm_80+ only — target is sm_103 BASE)
// ============================================================================
__device__ __forceinline__ uint32_t smem_u32(const void* p) {
    uint32_t a;
    asm("{ .reg .u64 t; cvta.to.shared.u64 t, %1; cvt.u32.u64 %0, t; }"
        : "=r"(a) : "l"(p));
    return a;
}

__device__ __forceinline__ void cp_async16(uint32_t dst, const void* src) {
    asm volatile("cp.async.cg.shared.global [%0], [%1], 16;"
                 :: "r"(dst), "l"(src) : "memory");
}
__device__ __forceinline__ void cp_async8(uint32_t dst, const void* src) {
    asm volatile("cp.async.ca.shared.global [%0], [%1], 8;"
                 :: "r"(dst), "l"(src) : "memory");
}
#define CP_COMMIT() asm volatile("cp.async.commit_group;" ::: "memory")
#define CP_WAIT_3() asm volatile("cp.async.wait_group 3;" ::: "memory")
#define CP_WAIT_1() asm volatile("cp.async.wait_group 1;" ::: "memory")
#define CP_WAIT_0() asm volatile("cp.async.wait_group 0;" ::: "memory")

// D += A * B  (m16n8k16, f16 inputs, f32 accumulate)
__device__ __forceinline__ void mma16816(float c[4], const uint32_t a[4],
                                         uint32_t b0, uint32_t b1) {
    asm volatile(
        "mma.sync.aligned.m16n8k16.row.col.f32.f16.f16.f32 "
        "{%0,%1,%2,%3}, {%4,%5,%6,%7}, {%8,%9}, {%0,%1,%2,%3};"
        : "+f"(c[0]), "+f"(c[1]), "+f"(c[2]), "+f"(c[3])
        : "r"(a[0]), "r"(a[1]), "r"(a[2]), "r"(a[3]), "r"(b0), "r"(b1));
}

// 2 bits -> half2 {bit0 ? 1.0h : 0, bit1 ? 1.0h : 0}
__device__ __forceinline__ uint32_t expand2(uint32_t y) {
    uint32_t x = y & 3u;
    return (x & 1u) * 0x3C00u + (x & 2u) * 0x1E000000u;
}

// GEMM2 tiles: 128 rows x 32 k-halves, row stride 40 halves (80 B).
#define TSTRIDE   40
#define TILE_B    10240

// GEMM1 tiles: 128 rows x 64 k-halves, row stride 72 halves (144 B).
// Frag loads: banks = lane + const -> conflict-free (verified R12).
#define G1_STRIDE  72
#define G1_BTILE   18432               // 128*144
#define G1_A_OFF   0                   // expanded fp16 A tile, 18432 B
#define G1_B_OFF   18432               // + stage*18432, 4 stages
#define G1_APK_OFF (18432 + 4*18432)   // 92160; + stage*1024, 4 stages
#define G1_SMEM    (92160 + 4*1024)    // 96256

// ============================================================================
// Kernel 0: zero degree accumulator
// ============================================================================
__global__ void zero_deg_kernel() {
    int i = blockIdx.x * blockDim.x + threadIdx.x;
    if (i < N_NODES) g_deg[i] = 0.0f;
}

// ============================================================================
// Kernel 1: transpose + hi/lo fp16 split.  in[R][C] fp32 -> out[C][R] half x2
// ============================================================================
__global__ void transpose_split_kernel(const float* __restrict__ in,
                                       int R, int C, int which)
{
    __half* outH = which ? g_WhT : g_XhT;
    __half* outL = which ? g_WlT : g_XlT;
    __shared__ float tile[64][65];
    int r0 = blockIdx.y * 64;
    int c0 = blockIdx.x * 64;
    int tid = threadIdx.x;   // 256

    #pragma unroll
    for (int q = 0; q < 4; ++q) {
        int lin = q * 256 + tid;
        int r = lin >> 4;
        int c = (lin & 15) << 2;
        float4 v = *(const float4*)(in + (size_t)(r0 + r) * C + (c0 + c));
        tile[r][c] = v.x; tile[r][c+1] = v.y; tile[r][c+2] = v.z; tile[r][c+3] = v.w;
    }
    __syncthreads();

    int c = tid >> 2;
    #pragma unroll
    for (int sg = (tid & 3); sg < 8; sg += 4) {
        int rb = sg * 8;
        __align__(16) __half h[8];
        __align__(16) __half l[8];
        #pragma unroll
        for (int q = 0; q < 8; ++q) {
            float v = tile[rb + q][c];
            __half hh = __float2half_rn(v);
            h[q] = hh;
            l[q] = __float2half_rn(v - __half2float(hh));
        }
        *(uint4*)(outH + (size_t)(c0 + c) * R + r0 + rb) = *(const uint4*)h;
        *(uint4*)(outL + (size_t)(c0 + c) * R + r0 + rb) = *(const uint4*)l;
    }
}

// ============================================================================
// Kernel 2: adj int32 [N][N] -> bit-packed adjP + in-degree (exact int sums)
// No fp16 adjT materialization: 256 MB read + 8 MB write only.
// ============================================================================
__global__ void pack_adj_kernel(const int* __restrict__ adj)
{
    __shared__ int tile[64][65];
    int i0 = blockIdx.y * 64;
    int j0 = blockIdx.x * 64;
    int tid = threadIdx.x;      // 256
    int wid = tid >> 5;
    int lane = tid & 31;

    #pragma unroll
    for (int q = 0; q < 4; ++q) {
        int lin = q * 256 + tid;
        int r = lin >> 4;
        int c = (lin & 15) << 2;
        int4 v = *(const int4*)(adj + (size_t)(i0 + r) * N_NODES + (j0 + c));
        tile[r][c] = v.x; tile[r][c+1] = v.y; tile[r][c+2] = v.z; tile[r][c+3] = v.w;
    }
    __syncthreads();

    {   // exact integer partial column sums
        int c = tid & 63;
        int ch = tid >> 6;
        int s = 0;
        #pragma unroll
        for (int r = ch * 16; r < ch * 16 + 16; ++r) s += tile[r][c];
        atomicAdd(g_deg + j0 + c, (float)s);
    }

    // pack: warp w handles 8 columns; bit l of word = adj[i0(+32)+l][j]
    #pragma unroll
    for (int t = 0; t < 8; ++t) {
        int jc = wid * 8 + t;
        unsigned b0 = __ballot_sync(0xFFFFFFFFu, tile[lane][jc] != 0);
        unsigned b1 = __ballot_sync(0xFFFFFFFFu, tile[32 + lane][jc] != 0);
        if (lane == 0) {
            size_t base = (size_t)(j0 + jc) * NW + (i0 >> 5);
            g_adjP[base]     = b0;
            g_adjP[base + 1] = b1;
        }
    }
}

// ============================================================================
// Kernel 3: GEMM1 — support[j,f] = sum_i adj[i][j] * Xh[i][f]
// A comes in BIT-PACKED (1 KB/chunk), expanded to fp16 in SMEM once per chunk
// (shared by all warps). Grid (4 f, 64 j); 128 threads = 4 warps (2m x 2n),
// warp tile 64x64; K chunk 64; 4-stage cp.async pipeline; 2 CTAs/SM.
// ============================================================================
__device__ __forceinline__ void g1_load(uint32_t sb, int s, int kc,
                                        int j0, int f0, int tid)
{
    const uint32_t bbase = sb + G1_B_OFF + (s & 3) * G1_BTILE;
    #pragma unroll
    for (int q = 0; q < 8; ++q) {               // 1024 B-segs / 128 threads
        int idx = q * 128 + tid;
        int r   = idx >> 3;
        int seg = idx & 7;
        const __half* src = g_XhT + (size_t)(f0 + r) * N_NODES + kc * 64 + seg * 8;
        cp_async16(bbase + r * 144 + seg * 16, src);
    }
    const uint32_t abase = sb + G1_APK_OFF + (s & 3) * 1024;
    const uint32_t* srcA = g_adjP + (size_t)(j0 + tid) * NW + kc * 2;
    cp_async8(abase + tid * 8, srcA);
    CP_COMMIT();
}

__global__ void __launch_bounds__(128, 2) gemm1_kernel()
{
    extern __shared__ char smem[];
    const uint32_t sb = smem_u32(smem);
    const int tid = threadIdx.x;
    const int wid = tid >> 5;
    const int lane = tid & 31;
    const int warp_m = wid & 1;        // 2
    const int warp_n = wid >> 1;       // 2
    const int gid  = lane >> 2;
    const int tig2 = (lane & 3) * 2;
    const int f0 = blockIdx.x * 128;
    const int j0 = blockIdx.y * 128;

    float acc[4][8][4];
    #pragma unroll
    for (int mi = 0; mi < 4; ++mi)
        #pragma unroll
        for (int ni = 0; ni < 8; ++ni)
            #pragma unroll
            for (int q = 0; q < 4; ++q) acc[mi][ni][q] = 0.0f;

    const int NC = N_NODES / 64;    // 128
    g1_load(sb, 0, 0, j0, f0, tid);
    g1_load(sb, 1, 1, j0, f0, tid);
    g1_load(sb, 2, 2, j0, f0, tid);

    for (int c = 0; c < NC; ++c) {
        __syncthreads();                       // A tile free + old B consumed
        if (c + 3 < NC) g1_load(sb, c + 3, c + 3, j0, f0, tid);
        CP_WAIT_3();                           // stage c landed (this thread)

        // expand packed A chunk -> fp16 tile (thread t = row t)
        {
            const uint2 w = *(const uint2*)(smem + G1_APK_OFF + (c & 3) * 1024 + tid * 8);
            #pragma unroll
            for (int q = 0; q < 8; ++q) {
                uint32_t word = (q < 4) ? w.x : w.y;
                int pb = (q & 3) * 8;
                uint4 v;
                v.x = expand2(word >> (pb + 0));
                v.y = expand2(word >> (pb + 2));
                v.z = expand2(word >> (pb + 4));
                v.w = expand2(word >> (pb + 6));
                *(uint4*)(smem + G1_A_OFF + tid * 144 + q * 16) = v;
            }
        }
        __syncthreads();                       // A ready; B writes visible

        const __half* As = (const __half*)(smem + G1_A_OFF);
        const __half* Bs = (const __half*)(smem + G1_B_OFF + (c & 3) * G1_BTILE);

        #pragma unroll
        for (int kk = 0; kk < 4; ++kk) {
            const int k0 = kk * 16;
            uint32_t a[4][4];
            #pragma unroll
            for (int mi = 0; mi < 4; ++mi) {
                int r0 = warp_m * 64 + mi * 16 + gid;
                a[mi][0] = *(const uint32_t*)&As[r0 * G1_STRIDE + k0 + tig2];
                a[mi][1] = *(const uint32_t*)&As[(r0 + 8) * G1_STRIDE + k0 + tig2];
                a[mi][2] = *(const uint32_t*)&As[r0 * G1_STRIDE + k0 + 8 + tig2];
                a[mi][3] = *(const uint32_t*)&As[(r0 + 8) * G1_STRIDE + k0 + 8 + tig2];
            }
            #pragma unroll
            for (int ni = 0; ni < 8; ++ni) {
                int nr = warp_n * 64 + ni * 8 + gid;
                uint32_t b0 = *(const uint32_t*)&Bs[nr * G1_STRIDE + k0 + tig2];
                uint32_t b1 = *(const uint32_t*)&Bs[nr * G1_STRIDE + k0 + 8 + tig2];
                #pragma unroll
                for (int mi = 0; mi < 4; ++mi)
                    mma16816(acc[mi][ni], a[mi], b0, b1);
            }
        }
    }

    // Epilogue: split fp32 support into Sh/Sl fp16
    #pragma unroll
    for (int mi = 0; mi < 4; ++mi) {
        #pragma unroll
        for (int ni = 0; ni < 8; ++ni) {
            int j = j0 + warp_m * 64 + mi * 16 + gid;
            int f = f0 + warp_n * 64 + ni * 8 + tig2;
            float v0 = acc[mi][ni][0], v1 = acc[mi][ni][1];
            float v2 = acc[mi][ni][2], v3 = acc[mi][ni][3];
            __half h0 = __float2half_rn(v0), h1 = __float2half_rn(v1);
            __half h2 = __float2half_rn(v2), h3 = __float2half_rn(v3);
            __half l0 = __float2half_rn(v0 - __half2float(h0));
            __half l1 = __float2half_rn(v1 - __half2float(h1));
            __half l2 = __float2half_rn(v2 - __half2float(h2));
            __half l3 = __float2half_rn(v3 - __half2float(h3));
            *(__half2*)&g_Sh[(size_t)j * F_DIM + f]       = __halves2half2(h0, h1);
            *(__half2*)&g_Sl[(size_t)j * F_DIM + f]       = __halves2half2(l0, l1);
            *(__half2*)&g_Sh[(size_t)(j + 8) * F_DIM + f] = __halves2half2(h2, h3);
            *(__half2*)&g_Sl[(size_t)(j + 8) * F_DIM + f] = __halves2half2(l2, l3);
        }
    }
}

// ============================================================================
// Kernel 4: GEMM2 + epilogue (unchanged from R12)
// out[j,g] = relu( rsqrt(max(deg_j,1)) * sum_f (Sh+Sl)[j,f] (Wh+Wl)T[g,f] )
// ============================================================================
#define G2_BUF_B   (4 * TILE_B)            // 40960
#define G2_SMEM    (2 * G2_BUF_B)          // 81920

__device__ __forceinline__ void g2_load(uint32_t sb, int buf, int kc,
                                        int j0, int g0, int tid)
{
    const uint32_t base = sb + buf * G2_BUF_B;
    #pragma unroll
    for (int q = 0; q < 8; ++q) {               // 2048 16B segs / 256 threads
        int idx = q * 256 + tid;
        int t   = idx >> 9;                     // 0..3: Ah, Al, Bh, Bl
        int rem = idx & 511;
        int r   = rem >> 2;
        int seg = rem & 3;
        const __half* src;
        if (t == 0)      src = g_Sh  + (size_t)(j0 + r) * F_DIM + kc * 32 + seg * 8;
        else if (t == 1) src = g_Sl  + (size_t)(j0 + r) * F_DIM + kc * 32 + seg * 8;
        else if (t == 2) src = g_WhT + (size_t)(g0 + r) * F_DIM + kc * 32 + seg * 8;
        else             src = g_WlT + (size_t)(g0 + r) * F_DIM + kc * 32 + seg * 8;
        cp_async16(base + t * TILE_B + r * 80 + seg * 16, src);
    }
    CP_COMMIT();
}

__global__ void __launch_bounds__(256, 2) gemm2_kernel(float* __restrict__ out)
{
    extern __shared__ char smem[];
    const uint32_t sb = smem_u32(smem);
    const int tid = threadIdx.x;
    const int wid = tid >> 5;
    const int lane = tid & 31;
    const int warp_m = wid & 3;
    const int warp_n = wid >> 2;
    const int gid  = lane >> 2;
    const int tig2 = (lane & 3) * 2;
    const int g0 = blockIdx.x * 128;
    const int j0 = blockIdx.y * 128;

    float acc[2][8][4];
    #pragma unroll
    for (int mi = 0; mi < 2; ++mi)
        #pragma unroll
        for (int ni = 0; ni < 8; ++ni)
            #pragma unroll
            for (int q = 0; q < 4; ++q) acc[mi][ni][q] = 0.0f;

    const int NC = F_DIM / 32;   // 16
    g2_load(sb, 0, 0, j0, g0, tid);

    for (int c = 0; c < NC; ++c) {
        if (c + 1 < NC) { g2_load(sb, (c + 1) & 1, c + 1, j0, g0, tid); CP_WAIT_1(); }
        else            { CP_WAIT_0(); }
        __syncthreads();

        const __half* Ahs = (const __half*)(smem + (c & 1) * G2_BUF_B);
        const __half* Als = Ahs + TILE_B / 2;
        const __half* Bhs = Ahs + TILE_B;
        const __half* Bls = Ahs + 3 * TILE_B / 2;

        #pragma unroll
        for (int kk = 0; kk < 32; kk += 16) {
            uint32_t ah[2][4], al[2][4];
            #pragma unroll
            for (int mi = 0; mi < 2; ++mi) {
                int r0 = warp_m * 32 + mi * 16 + gid;
                ah[mi][0] = *(const uint32_t*)&Ahs[r0 * TSTRIDE + kk + tig2];
                ah[mi][1] = *(const uint32_t*)&Ahs[(r0 + 8) * TSTRIDE + kk + tig2];
                ah[mi][2] = *(const uint32_t*)&Ahs[r0 * TSTRIDE + kk + 8 + tig2];
                ah[mi][3] = *(const uint32_t*)&Ahs[(r0 + 8) * TSTRIDE + kk + 8 + tig2];
                al[mi][0] = *(const uint32_t*)&Als[r0 * TSTRIDE + kk + tig2];
                al[mi][1] = *(const uint32_t*)&Als[(r0 + 8) * TSTRIDE + kk + tig2];
                al[mi][2] = *(const uint32_t*)&Als[r0 * TSTRIDE + kk + 8 + tig2];
                al[mi][3] = *(const uint32_t*)&Als[(r0 + 8) * TSTRIDE + kk + 8 + tig2];
            }
            #pragma unroll
            for (int ni = 0; ni < 8; ++ni) {
                int nr = warp_n * 64 + ni * 8 + gid;
                uint32_t bh0 = *(const uint32_t*)&Bhs[nr * TSTRIDE + kk + tig2];
                uint32_t bh1 = *(const uint32_t*)&Bhs[nr * TSTRIDE + kk + 8 + tig2];
                uint32_t bl0 = *(const uint32_t*)&Bls[nr * TSTRIDE + kk + tig2];
                uint32_t bl1 = *(const uint32_t*)&Bls[nr * TSTRIDE + kk + 8 + tig2];
                #pragma unroll
                for (int mi = 0; mi < 2; ++mi) {
                    mma16816(acc[mi][ni], ah[mi], bh0, bh1);   // hh
                    mma16816(acc[mi][ni], ah[mi], bl0, bl1);   // hl
                    mma16816(acc[mi][ni], al[mi], bh0, bh1);   // lh
                }
            }
        }
        __syncthreads();
    }

    #pragma unroll
    for (int mi = 0; mi < 2; ++mi) {
        int j = j0 + warp_m * 32 + mi * 16 + gid;
        float nrm0 = rsqrtf(fmaxf(g_deg[j], 1.0f));
        float nrm1 = rsqrtf(fmaxf(g_deg[j + 8], 1.0f));
        #pragma unroll
        for (int ni = 0; ni < 8; ++ni) {
            int g = g0 + warp_n * 64 + ni * 8 + tig2;
            float2 v0, v1;
            v0.x = fmaxf(acc[mi][ni][0] * nrm0, 0.0f);
            v0.y = fmaxf(acc[mi][ni][1] * nrm0, 0.0f);
            v1.x = fmaxf(acc[mi][ni][2] * nrm1, 0.0f);
            v1.y = fmaxf(acc[mi][ni][3] * nrm1, 0.0f);
            *(float2*)(out + (size_t)j * F_DIM + g)       = v0;
            *(float2*)(out + (size_t)(j + 8) * F_DIM + g) = v1;
        }
    }
}

// ============================================================================
// Launch
// ============================================================================
extern "C" void kernel_launch(void* const* d_in, const int* in_sizes, int n_in,
                              void* d_out, int out_size)
{
    (void)in_sizes; (void)n_in; (void)out_size;
    const float* X      = (const float*)d_in[0];   // [8192, 512]
    const int*   adj    = (const int*)d_in[1];     // [8192, 8192]
    const float* weight = (const float*)d_in[2];   // [512, 512]
    float* out = (float*)d_out;                    // [8192, 512]

    cudaFuncSetAttribute(gemm1_kernel,
        cudaFuncAttributeMaxDynamicSharedMemorySize, G1_SMEM);
    cudaFuncSetAttribute(gemm2_kernel,
        cudaFuncAttributeMaxDynamicSharedMemorySize, G2_SMEM);

    zero_deg_kernel<<<N_NODES / 256, 256>>>();

    {   // X: [8192, 512] -> XhT/XlT [512, 8192]
        dim3 grid(F_DIM / 64, N_NODES / 64);
        transpose_split_kernel<<<grid, 256>>>(X, N_NODES, F_DIM, 0);
    }
    {   // W: [512, 512] -> WhT/WlT [512, 512]
        dim3 grid(F_DIM / 64, F_DIM / 64);
        transpose_split_kernel<<<grid, 256>>>(weight, F_DIM, F_DIM, 1);
    }
    {   // adj -> bit-packed adjP + degrees
        dim3 grid(N_NODES / 64, N_NODES / 64);
        pack_adj_kernel<<<grid, 256>>>(adj);
    }

    {   // GEMM1: support = adjT @ Xh  (bit-packed A)
        dim3 grid(F_DIM / 128, N_NODES / 128);   // (4, 64)
        gemm1_kernel<<<grid, 128, G1_SMEM>>>();
    }
    {   // GEMM2 + norm + relu
        dim3 grid(F_DIM / 128, N_NODES / 128);   // (4, 64)
        gemm2_kernel<<<grid, 256, G2_SMEM>>>(out);
    }
}

// round 16
// speedup vs baseline: 2.0363x; 1.1525x over previous
#include <cuda_runtime.h>
#include <cuda_fp16.h>
#include <cstdint>
#include <cstddef>

#define N_NODES 8192
#define F_DIM   512
#define NW      (N_NODES / 32)   // 256 packed words per row

// ============================================================================
// Scratch (device globals — no allocation anywhere)
// ============================================================================
__device__ uint32_t g_adjP[(size_t)N_NODES * NW];      // bit b of [j][w] = adj[32w+b][j]
__device__ __half g_XhT[(size_t)F_DIM * N_NODES];      // X fp16, transposed [f][i]
__device__ __half g_WhT[(size_t)F_DIM * F_DIM];        // W hi, transposed [g][f]
__device__ __half g_WlT[(size_t)F_DIM * F_DIM];        // W lo, transposed [g][f]
__device__ __half g_Sh[(size_t)N_NODES * F_DIM];       // support fp16 [j][f]
__device__ float  g_deg[N_NODES];                      // in-degree per j

// ============================================================================
// Helpers (sm_80+ only — target is sm_103 BASE)
// ============================================================================
__device__ __forceinline__ uint32_t smem_u32(const void* p) {
    uint32_t a;
    asm("{ .reg .u64 t; cvta.to.shared.u64 t, %1; cvt.u32.u64 %0, t; }"
        : "=r"(a) : "l"(p));
    return a;
}

__device__ __forceinline__ void cp_async16(uint32_t dst, const void* src) {
    asm volatile("cp.async.cg.shared.global [%0], [%1], 16;"
                 :: "r"(dst), "l"(src) : "memory");
}
__device__ __forceinline__ void cp_async8(uint32_t dst, const void* src) {
    asm volatile("cp.async.ca.shared.global [%0], [%1], 8;"
                 :: "r"(dst), "l"(src) : "memory");
}
#define CP_COMMIT() asm volatile("cp.async.commit_group;" ::: "memory")
#define CP_WAIT_1() asm volatile("cp.async.wait_group 1;" ::: "memory")
#define CP_WAIT_0() asm volatile("cp.async.wait_group 0;" ::: "memory")

// D += A * B  (m16n8k16, f16 inputs, f32 accumulate)
__device__ __forceinline__ void mma16816(float c[4], const uint32_t a[4],
                                         uint32_t b0, uint32_t b1) {
    asm volatile(
        "mma.sync.aligned.m16n8k16.row.col.f32.f16.f16.f32 "
        "{%0,%1,%2,%3}, {%4,%5,%6,%7}, {%8,%9}, {%0,%1,%2,%3};"
        : "+f"(c[0]), "+f"(c[1]), "+f"(c[2]), "+f"(c[3])
        : "r"(a[0]), "r"(a[1]), "r"(a[2]), "r"(a[3]), "r"(b0), "r"(b1));
}

#define LDSM4(r, addr) \
    asm volatile("ldmatrix.sync.aligned.m8n8.x4.shared.b16 {%0,%1,%2,%3}, [%4];" \
        : "=r"((r)[0]), "=r"((r)[1]), "=r"((r)[2]), "=r"((r)[3]) : "r"(addr))

// 2 bits -> half2 {bit0 ? 1.0h : 0, bit1 ? 1.0h : 0}
__device__ __forceinline__ uint32_t expand2(uint32_t y) {
    uint32_t x = y & 3u;
    return (x & 1u) * 0x3C00u + (x & 2u) * 0x1E000000u;
}

// GEMM2 tiles: 128 rows x 32 k-halves, row stride 40 halves (80 B).
#define TSTRIDE   40
#define TILE_B    10240

// GEMM1 tiles: 128 rows x 64 k-halves, row stride 72 halves (144 B).
#define G1_STRIDE  72
#define G1_BTILE   18432               // 128*144
#define G1_A_OFF   0                   // expanded A, 2 buffers
#define G1_B_OFF   (2 * G1_BTILE)      // 36864; + stage*18432, 3 stages
#define G1_APK_OFF (G1_B_OFF + 3 * G1_BTILE)   // 92160; + stage*1024, 3 stages
#define G1_SMEM    (G1_APK_OFF + 3 * 1024)     // 95232

// ============================================================================
// Kernel 0: zero degree accumulator
// ============================================================================
__global__ void zero_deg_kernel() {
    int i = blockIdx.x * blockDim.x + threadIdx.x;
    if (i < N_NODES) g_deg[i] = 0.0f;
}

// ============================================================================
// Kernel 1: transpose (+ optional hi/lo split).  in[R][C] fp32 -> [C][R] half
// which==0 -> g_XhT only;  which==1 -> g_WhT + g_WlT
// ============================================================================
__global__ void transpose_split_kernel(const float* __restrict__ in,
                                       int R, int C, int which)
{
    __half* outH = which ? g_WhT : g_XhT;
    __shared__ float tile[64][65];
    int r0 = blockIdx.y * 64;
    int c0 = blockIdx.x * 64;
    int tid = threadIdx.x;   // 256

    #pragma unroll
    for (int q = 0; q < 4; ++q) {
        int lin = q * 256 + tid;
        int r = lin >> 4;
        int c = (lin & 15) << 2;
        float4 v = *(const float4*)(in + (size_t)(r0 + r) * C + (c0 + c));
        tile[r][c] = v.x; tile[r][c+1] = v.y; tile[r][c+2] = v.z; tile[r][c+3] = v.w;
    }
    __syncthreads();

    int c = tid >> 2;
    #pragma unroll
    for (int sg = (tid & 3); sg < 8; sg += 4) {
        int rb = sg * 8;
        __align__(16) __half h[8];
        #pragma unroll
        for (int q = 0; q < 8; ++q)
            h[q] = __float2half_rn(tile[rb + q][c]);
        *(uint4*)(outH + (size_t)(c0 + c) * R + r0 + rb) = *(const uint4*)h;
        if (which) {
            __align__(16) __half l[8];
            #pragma unroll
            for (int q = 0; q < 8; ++q)
                l[q] = __float2half_rn(tile[rb + q][c] - __half2float(h[q]));
            *(uint4*)(g_WlT + (size_t)(c0 + c) * R + r0 + rb) = *(const uint4*)l;
        }
    }
}

// ============================================================================
// Kernel 2: adj int32 [N][N] -> bit-packed adjP + in-degree via popc
// ============================================================================
__global__ void pack_adj_kernel(const int* __restrict__ adj)
{
    __shared__ int tile[64][65];
    int i0 = blockIdx.y * 64;
    int j0 = blockIdx.x * 64;
    int tid = threadIdx.x;      // 256
    int wid = tid >> 5;
    int lane = tid & 31;

    #pragma unroll
    for (int q = 0; q < 4; ++q) {
        int lin = q * 256 + tid;
        int r = lin >> 4;
        int c = (lin & 15) << 2;
        int4 v = *(const int4*)(adj + (size_t)(i0 + r) * N_NODES + (j0 + c));
        tile[r][c] = v.x; tile[r][c+1] = v.y; tile[r][c+2] = v.z; tile[r][c+3] = v.w;
    }
    __syncthreads();

    #pragma unroll
    for (int t = 0; t < 8; ++t) {
        int jc = wid * 8 + t;
        unsigned b0 = __ballot_sync(0xFFFFFFFFu, tile[lane][jc] != 0);
        unsigned b1 = __ballot_sync(0xFFFFFFFFu, tile[32 + lane][jc] != 0);
        if (lane == 0) {
            size_t base = (size_t)(j0 + jc) * NW + (i0 >> 5);
            g_adjP[base]     = b0;
            g_adjP[base + 1] = b1;
            atomicAdd(g_deg + j0 + jc, (float)(__popc(b0) + __popc(b1)));
        }
    }
}

// ============================================================================
// Kernel 3: GEMM1 — support[j,f] = sum_i adj[i][j] * Xh[i][f]
// Bit-packed A expanded to fp16 in SMEM (double-buffered), ONE sync/chunk,
// 3-stage cp.async pipeline, ldmatrix.x4 fragment loads.
// Grid (4 f, 64 j); 128 threads = 4 warps (2m x 2n), warp tile 64x64, K=64.
// ============================================================================
__device__ __forceinline__ void g1_load(uint32_t sb, int s, int j0, int f0, int tid)
{
    const int stage = s % 3;
    const uint32_t bbase = sb + G1_B_OFF + stage * G1_BTILE;
    #pragma unroll
    for (int q = 0; q < 8; ++q) {               // 1024 B-segs / 128 threads
        int idx = q * 128 + tid;
        int r   = idx >> 3;
        int seg = idx & 7;
        const __half* src = g_XhT + (size_t)(f0 + r) * N_NODES + s * 64 + seg * 8;
        cp_async16(bbase + r * 144 + seg * 16, src);
    }
    const uint32_t abase = sb + G1_APK_OFF + stage * 1024;
    cp_async8(abase + tid * 8, g_adjP + (size_t)(j0 + tid) * NW + s * 2);
    CP_COMMIT();
}

__global__ void __launch_bounds__(128, 2) gemm1_kernel()
{
    extern __shared__ char smem[];
    const uint32_t sb = smem_u32(smem);
    const int tid = threadIdx.x;
    const int wid = tid >> 5;
    const int lane = tid & 31;
    const int warp_m = wid & 1;        // 2
    const int warp_n = wid >> 1;       // 2
    const int gid  = lane >> 2;
    const int tig2 = (lane & 3) * 2;
    const int f0 = blockIdx.x * 128;
    const int j0 = blockIdx.y * 128;

    // per-lane ldmatrix base offsets (bytes, within a tile)
    const uint32_t aOff = (uint32_t)((warp_m * 64 + (lane & 15)) * G1_STRIDE
                                     + (lane >> 4) * 8) * 2;
    const int bQuad = lane >> 3;
    const uint32_t bOff = (uint32_t)((warp_n * 64 + (bQuad >> 1) * 8 + (lane & 7)) * G1_STRIDE
                                     + (bQuad & 1) * 8) * 2;

    float acc[4][8][4];
    #pragma unroll
    for (int mi = 0; mi < 4; ++mi)
        #pragma unroll
        for (int ni = 0; ni < 8; ++ni)
            #pragma unroll
            for (int q = 0; q < 4; ++q) acc[mi][ni][q] = 0.0f;

    const int NC = N_NODES / 64;    // 128
    g1_load(sb, 0, j0, f0, tid);
    g1_load(sb, 1, j0, f0, tid);

    for (int c = 0; c < NC; ++c) {
        CP_WAIT_1();                           // group c retired (own copies)

        // expand own packed word (loaded by THIS thread) -> A row tid
        {
            const uint2 w = *(const uint2*)(smem + G1_APK_OFF + (c % 3) * 1024 + tid * 8);
            char* arow = smem + G1_A_OFF + (c & 1) * G1_BTILE + tid * 144;
            #pragma unroll
            for (int q = 0; q < 8; ++q) {
                uint32_t word = (q < 4) ? w.x : w.y;
                int pb = (q & 3) * 8;
                uint4 v;
                v.x = expand2(word >> (pb + 0));
                v.y = expand2(word >> (pb + 2));
                v.z = expand2(word >> (pb + 4));
                v.w = expand2(word >> (pb + 6));
                *(uint4*)(arow + q * 16) = v;
            }
        }
        __syncthreads();                       // A(c), B(c) visible; old reads done

        if (c + 2 < NC) g1_load(sb, c + 2, j0, f0, tid);
        else            CP_COMMIT();           // keep group counts aligned

        const uint32_t aPtr = sb + G1_A_OFF + (c & 1) * G1_BTILE + aOff;
        const uint32_t bPtr = sb + G1_B_OFF + (c % 3) * G1_BTILE + bOff;

        #pragma unroll
        for (int kk = 0; kk < 4; ++kk) {
            uint32_t a[4][4];
            #pragma unroll
            for (int mi = 0; mi < 4; ++mi)
                LDSM4(a[mi], aPtr + mi * 2304 + kk * 32);     // 16 rows * 144B = 2304
            uint32_t b[4][4];
            #pragma unroll
            for (int p = 0; p < 4; ++p)
                LDSM4(b[p], bPtr + p * 2304 + kk * 32);
            #pragma unroll
            for (int mi = 0; mi < 4; ++mi)
                #pragma unroll
                for (int p = 0; p < 4; ++p) {
                    mma16816(acc[mi][2 * p],     a[mi], b[p][0], b[p][1]);
                    mma16816(acc[mi][2 * p + 1], a[mi], b[p][2], b[p][3]);
                }
        }
    }

    // Epilogue: round support to fp16 (single), store
    #pragma unroll
    for (int mi = 0; mi < 4; ++mi) {
        #pragma unroll
        for (int ni = 0; ni < 8; ++ni) {
            int j = j0 + warp_m * 64 + mi * 16 + gid;
            int f = f0 + warp_n * 64 + ni * 8 + tig2;
            *(__half2*)&g_Sh[(size_t)j * F_DIM + f] =
                __halves2half2(__float2half_rn(acc[mi][ni][0]),
                               __float2half_rn(acc[mi][ni][1]));
            *(__half2*)&g_Sh[(size_t)(j + 8) * F_DIM + f] =
                __halves2half2(__float2half_rn(acc[mi][ni][2]),
                               __float2half_rn(acc[mi][ni][3]));
        }
    }
}

// ============================================================================
// Kernel 4: GEMM2 + epilogue
// out[j,g] = relu( rsqrt(max(deg_j,1)) * sum_f Sh[j,f] * (Wh+Wl)T[g,f] )
// 2 products (S*Wh + S*Wl); 3 tiles/chunk; double-buffered.
// ============================================================================
#define G2_BUF_B   (3 * TILE_B)            // 30720
#define G2_SMEM    (2 * G2_BUF_B)          // 61440

__device__ __forceinline__ void g2_load(uint32_t sb, int buf, int kc,
                                        int j0, int g0, int tid)
{
    const uint32_t base = sb + buf * G2_BUF_B;
    #pragma unroll
    for (int q = 0; q < 6; ++q) {               // 1536 16B segs / 256 threads
        int idx = q * 256 + tid;
        int t   = idx >> 9;                     // 0: Sh, 1: Wh, 2: Wl
        int rem = idx & 511;
        int r   = rem >> 2;
        int seg = rem & 3;
        const __half* src;
        if (t == 0)      src = g_Sh  + (size_t)(j0 + r) * F_DIM + kc * 32 + seg * 8;
        else if (t == 1) src = g_WhT + (size_t)(g0 + r) * F_DIM + kc * 32 + seg * 8;
        else             src = g_WlT + (size_t)(g0 + r) * F_DIM + kc * 32 + seg * 8;
        cp_async16(base + t * TILE_B + r * 80 + seg * 16, src);
    }
    CP_COMMIT();
}

__global__ void __launch_bounds__(256, 2) gemm2_kernel(float* __restrict__ out)
{
    extern __shared__ char smem[];
    const uint32_t sb = smem_u32(smem);
    const int tid = threadIdx.x;
    const int wid = tid >> 5;
    const int lane = tid & 31;
    const int warp_m = wid & 3;
    const int warp_n = wid >> 2;
    const int gid  = lane >> 2;
    const int tig2 = (lane & 3) * 2;
    const int g0 = blockIdx.x * 128;
    const int j0 = blockIdx.y * 128;

    float acc[2][8][4];
    #pragma unroll
    for (int mi = 0; mi < 2; ++mi)
        #pragma unroll
        for (int ni = 0; ni < 8; ++ni)
            #pragma unroll
            for (int q = 0; q < 4; ++q) acc[mi][ni][q] = 0.0f;

    const int NC = F_DIM / 32;   // 16
    g2_load(sb, 0, 0, j0, g0, tid);

    for (int c = 0; c < NC; ++c) {
        if (c + 1 < NC) { g2_load(sb, (c + 1) & 1, c + 1, j0, g0, tid); CP_WAIT_1(); }
        else            { CP_WAIT_0(); }
        __syncthreads();

        const __half* Ahs = (const __half*)(smem + (c & 1) * G2_BUF_B);
        const __half* Bhs = Ahs + TILE_B / 2;
        const __half* Bls = Ahs + TILE_B;

        #pragma unroll
        for (int kk = 0; kk < 32; kk += 16) {
            uint32_t ah[2][4];
            #pragma unroll
            for (int mi = 0; mi < 2; ++mi) {
                int r0 = warp_m * 32 + mi * 16 + gid;
                ah[mi][0] = *(const uint32_t*)&Ahs[r0 * TSTRIDE + kk + tig2];
                ah[mi][1] = *(const uint32_t*)&Ahs[(r0 + 8) * TSTRIDE + kk + tig2];
                ah[mi][2] = *(const uint32_t*)&Ahs[r0 * TSTRIDE + kk + 8 + tig2];
                ah[mi][3] = *(const uint32_t*)&Ahs[(r0 + 8) * TSTRIDE + kk + 8 + tig2];
            }
            #pragma unroll
            for (int ni = 0; ni < 8; ++ni) {
                int nr = warp_n * 64 + ni * 8 + gid;
                uint32_t bh0 = *(const uint32_t*)&Bhs[nr * TSTRIDE + kk + tig2];
                uint32_t bh1 = *(const uint32_t*)&Bhs[nr * TSTRIDE + kk + 8 + tig2];
                uint32_t bl0 = *(const uint32_t*)&Bls[nr * TSTRIDE + kk + tig2];
                uint32_t bl1 = *(const uint32_t*)&Bls[nr * TSTRIDE + kk + 8 + tig2];
                #pragma unroll
                for (int mi = 0; mi < 2; ++mi) {
                    mma16816(acc[mi][ni], ah[mi], bh0, bh1);   // S*Wh
                    mma16816(acc[mi][ni], ah[mi], bl0, bl1);   // S*Wl
                }
            }
        }
        __syncthreads();
    }

    #pragma unroll
    for (int mi = 0; mi < 2; ++mi) {
        int j = j0 + warp_m * 32 + mi * 16 + gid;
        float nrm0 = rsqrtf(fmaxf(g_deg[j], 1.0f));
        float nrm1 = rsqrtf(fmaxf(g_deg[j + 8], 1.0f));
        #pragma unroll
        for (int ni = 0; ni < 8; ++ni) {
            int g = g0 + warp_n * 64 + ni * 8 + tig2;
            float2 v0, v1;
            v0.x = fmaxf(acc[mi][ni][0] * nrm0, 0.0f);
            v0.y = fmaxf(acc[mi][ni][1] * nrm0, 0.0f);
            v1.x = fmaxf(acc[mi][ni][2] * nrm1, 0.0f);
            v1.y = fmaxf(acc[mi][ni][3] * nrm1, 0.0f);
            *(float2*)(out + (size_t)j * F_DIM + g)       = v0;
            *(float2*)(out + (size_t)(j + 8) * F_DIM + g) = v1;
        }
    }
}

// ============================================================================
// Launch — gemm1 placed 4th so ncu (-s 5 -c 1) captures it next round
// ============================================================================
extern "C" void kernel_launch(void* const* d_in, const int* in_sizes, int n_in,
                              void* d_out, int out_size)
{
    (void)in_sizes; (void)n_in; (void)out_size;
    const float* X      = (const float*)d_in[0];   // [8192, 512]
    const int*   adj    = (const int*)d_in[1];     // [8192, 8192]
    const float* weight = (const float*)d_in[2];   // [512, 512]
    float* out = (float*)d_out;                    // [8192, 512]

    cudaFuncSetAttribute(gemm1_kernel,
        cudaFuncAttributeMaxDynamicSharedMemorySize, G1_SMEM);
    cudaFuncSetAttribute(gemm2_kernel,
        cudaFuncAttributeMaxDynamicSharedMemorySize, G2_SMEM);

    zero_deg_kernel<<<N_NODES / 256, 256>>>();                       // 1
    {   // X: [8192, 512] -> XhT [512, 8192]                          // 2
        dim3 grid(F_DIM / 64, N_NODES / 64);
        transpose_split_kernel<<<grid, 256>>>(X, N_NODES, F_DIM, 0);
    }
    {   // adj -> bit-packed adjP + degrees                           // 3
        dim3 grid(N_NODES / 64, N_NODES / 64);
        pack_adj_kernel<<<grid, 256>>>(adj);
    }
    {   // GEMM1 (4th launch -> profiled)                             // 4
        dim3 grid(F_DIM / 128, N_NODES / 128);
        gemm1_kernel<<<grid, 128, G1_SMEM>>>();
    }
    {   // W: [512, 512] -> WhT/WlT                                   // 5
        dim3 grid(F_DIM / 64, F_DIM / 64);
        transpose_split_kernel<<<grid, 256>>>(weight, F_DIM, F_DIM, 1);
    }
    {   // GEMM2 + norm + relu                                        // 6
        dim3 grid(F_DIM / 128, N_NODES / 128);
        gemm2_kernel<<<grid, 256, G2_SMEM>>>(out);
    }
}